// round 10
// baseline (speedup 1.0000x reference)
#include <cuda_runtime.h>
#include <cuda_bf16.h>
#include <cstdint>

// LinearAttentionCell with T=1 reduces algebraically to out = x @ Wv^T.
// R10: mixed bf16 + fp8 Dekker GEMM.
//   x*w = xh*wh  (bf16 mma m16n8k16, exact inputs, fp32 acc)
//       + corr   (ONE fp8 mma m16n8k32 over concatenated K:
//                 A' = [xh_e4m3 | (xl*2^12)_e4m3],
//                 B' = [(wl*2^17)_e4m3 | (wh*2^5)_e4m3],
//                 both halves at scale 2^17 -> acc * 2^-17)
// Tensor instruction count drops 393216 -> 262144 (-33%), attacking the
// mma.sync issue-rate wall seen across R6/R8/R9 (~12us invariant).
// A fragments (bf16-hi + fp8) staged in smem per CTA; W converted in-register
// per stage into bf16-hi + fp8 lo/hi tiles (R8-validated swizzles).

#define KDIM 2048
#define NDIM 2048
#define MDIM 64
#define NT   64
#define SPLITK 16
#define KCH  128
#define KSTEPS 8      // k16 steps per CTA
#define NSTAGE 4      // k32 stages per CTA
#define GT   256      // 8 warps: 2 wrow(m32) x 4 wcol(n16)

#define XLS 4096.0f       // xl scale 2^12
#define WLS 131072.0f     // wl scale 2^17
#define WHS 32.0f         // wh scale 2^5
#define CINV (1.0f/131072.0f)

// x pre-split, fragment-ordered
__device__ __align__(16) uint4 g_ah [4 * 128 * 32];  // bf16 xh frags [mb][ks16][lane]
__device__ __align__(16) uint4 g_a8h[4 * 64 * 32];   // e4m3 xh frags [mb][s32][lane]
__device__ __align__(16) uint4 g_a8l[4 * 64 * 32];   // e4m3 (xl*2^12) frags

// dynamic smem layout (bytes)
#define SM_WH   0                      // [2 buf][2 kstep][2048]  bf16 W-hi tiles
#define SM_W8L  (SM_WH + 8192)         // [2 buf][2048]  e4m3 wl*2^17
#define SM_W8H  (SM_W8L + 4096)        // [2 buf][2048]  e4m3 wh*2^5
#define SM_ABH  (SM_W8H + 4096)        // [4 mb][8 ks][32] uint4  bf16 A frags
#define SM_A8H  (SM_ABH + 16384)       // [4 mb][4 s][32] uint4
#define SM_A8L  (SM_A8H + 8192)
#define SM_TOTAL (SM_A8L + 8192)       // 49152

__device__ __forceinline__ uint32_t cvt2(float hi_e, float lo_e) {
    uint32_t r;
    asm("cvt.rn.bf16x2.f32 %0, %1, %2;" : "=r"(r) : "f"(hi_e), "f"(lo_e));
    return r;
}

__device__ __forceinline__ uint32_t pack4_e4m3(float a, float b, float c, float d) {
    uint16_t lo, hi;   // byte0=a, byte1=b, byte2=c, byte3=d
    asm("cvt.rn.satfinite.e4m3x2.f32 %0, %1, %2;" : "=h"(lo) : "f"(b), "f"(a));
    asm("cvt.rn.satfinite.e4m3x2.f32 %0, %1, %2;" : "=h"(hi) : "f"(d), "f"(c));
    return (uint32_t)lo | ((uint32_t)hi << 16);
}

// bf16 hi/lo split of 4 consecutive values; also returns packed bf16 words
__device__ __forceinline__ void hi_lo4(float4 v, uint32_t& h01, uint32_t& h23,
                                       float* fh, float* fl) {
    h01 = cvt2(v.y, v.x);
    h23 = cvt2(v.w, v.z);
    fh[0] = __uint_as_float(h01 << 16);
    fh[1] = __uint_as_float(h01 & 0xFFFF0000u);
    fh[2] = __uint_as_float(h23 << 16);
    fh[3] = __uint_as_float(h23 & 0xFFFF0000u);
    fl[0] = v.x - fh[0]; fl[1] = v.y - fh[1];
    fl[2] = v.z - fh[2]; fl[3] = v.w - fh[3];
}

__device__ __forceinline__ void mma_bf16(float* d, const uint4& a,
                                         uint32_t b0, uint32_t b1) {
    asm volatile(
        "mma.sync.aligned.m16n8k16.row.col.f32.bf16.bf16.f32 "
        "{%0,%1,%2,%3}, {%4,%5,%6,%7}, {%8,%9}, {%0,%1,%2,%3};"
        : "+f"(d[0]), "+f"(d[1]), "+f"(d[2]), "+f"(d[3])
        : "r"(a.x), "r"(a.y), "r"(a.z), "r"(a.w), "r"(b0), "r"(b1));
}

__device__ __forceinline__ void mma_fp8(float* d, const uint4& a,
                                        uint32_t b0, uint32_t b1) {
    asm volatile(
        "mma.sync.aligned.m16n8k32.row.col.f32.e4m3.e4m3.f32 "
        "{%0,%1,%2,%3}, {%4,%5,%6,%7}, {%8,%9}, {%0,%1,%2,%3};"
        : "+f"(d[0]), "+f"(d[1]), "+f"(d[2]), "+f"(d[3])
        : "r"(a.x), "r"(a.y), "r"(a.z), "r"(a.w), "r"(b0), "r"(b1));
}

__device__ __forceinline__ void ldsm4(uint32_t* r, uint32_t addr) {
    asm volatile(
        "ldmatrix.sync.aligned.m8n8.x4.shared.b16 {%0,%1,%2,%3}, [%4];"
        : "=r"(r[0]), "=r"(r[1]), "=r"(r[2]), "=r"(r[3]) : "r"(addr));
}

// -------- kernel 1: x -> bf16-hi A fragments (k16 order) + zero out --------
__global__ __launch_bounds__(256)
void convert_x_kernel(const float* __restrict__ x, float4* __restrict__ outz) {
    int t = blockIdx.x * 256 + threadIdx.x;   // 0..16383
    outz[t] = make_float4(0.f, 0.f, 0.f, 0.f);
    outz[t + 16384] = make_float4(0.f, 0.f, 0.f, 0.f);

    int mb = t >> 12, ks = (t >> 5) & 127, lane = t & 31;
    int g = lane >> 2, tt = lane & 3;
    int m0 = mb * 16 + g, k0 = ks * 16 + 2 * tt;

    float2 p00 = *reinterpret_cast<const float2*>(&x[m0 * KDIM + k0]);
    float2 p10 = *reinterpret_cast<const float2*>(&x[(m0 + 8) * KDIM + k0]);
    float2 p01 = *reinterpret_cast<const float2*>(&x[m0 * KDIM + k0 + 8]);
    float2 p11 = *reinterpret_cast<const float2*>(&x[(m0 + 8) * KDIM + k0 + 8]);

    uint4 hi;
    hi.x = cvt2(p00.y, p00.x);
    hi.y = cvt2(p10.y, p10.x);
    hi.z = cvt2(p01.y, p01.x);
    hi.w = cvt2(p11.y, p11.x);
    g_ah[t] = hi;
}

// -------- kernel 2: x -> fp8 A' fragments (k32 order) --------
__global__ __launch_bounds__(256)
void convert_x8_kernel(const float* __restrict__ x) {
    int t = blockIdx.x * 256 + threadIdx.x;   // 0..8191 = [mb][s32][lane]
    int mb = t >> 11, s = (t >> 5) & 63, lane = t & 31;
    int g = lane >> 2, tt = lane & 3;
    int m0 = mb * 16 + g, kb = s * 32 + tt * 4;

    float4 f[4];
    f[0] = *reinterpret_cast<const float4*>(&x[m0 * KDIM + kb]);
    f[1] = *reinterpret_cast<const float4*>(&x[(m0 + 8) * KDIM + kb]);
    f[2] = *reinterpret_cast<const float4*>(&x[m0 * KDIM + kb + 16]);
    f[3] = *reinterpret_cast<const float4*>(&x[(m0 + 8) * KDIM + kb + 16]);

    uint32_t wh[4], wl[4];
#pragma unroll
    for (int i = 0; i < 4; i++) {
        uint32_t h01, h23; float fh[4], fl[4];
        hi_lo4(f[i], h01, h23, fh, fl);
        wh[i] = pack4_e4m3(fh[0], fh[1], fh[2], fh[3]);
        wl[i] = pack4_e4m3(fl[0] * XLS, fl[1] * XLS, fl[2] * XLS, fl[3] * XLS);
    }
    g_a8h[t] = make_uint4(wh[0], wh[1], wh[2], wh[3]);
    g_a8l[t] = make_uint4(wl[0], wl[1], wl[2], wl[3]);
}

// -------- kernel 3: mixed bf16+fp8 GEMM, atomic split-K --------
__global__ __launch_bounds__(GT, 2)
void gemm_kernel(const float* __restrict__ Wv, float* __restrict__ out) {
    extern __shared__ __align__(16) char smem[];
    uint8_t* WH  = reinterpret_cast<uint8_t*>(smem + SM_WH);   // [buf][kstep][2048]
    uint8_t* W8L = reinterpret_cast<uint8_t*>(smem + SM_W8L);  // [buf][2048]
    uint8_t* W8H = reinterpret_cast<uint8_t*>(smem + SM_W8H);
    uint4* ABH = reinterpret_cast<uint4*>(smem + SM_ABH);      // [mb][ks][lane]
    uint4* A8H = reinterpret_cast<uint4*>(smem + SM_A8H);      // [mb][s][lane]
    uint4* A8L = reinterpret_cast<uint4*>(smem + SM_A8L);

    const int tid  = threadIdx.x;
    const int lane = tid & 31;
    const int wid  = tid >> 5;
    const int wrow = wid >> 2;     // m32 group 0..1
    const int wcol = wid & 3;      // n16 group 0..3
    const int g  = lane >> 2;
    const int tt = lane & 3;

    const int n0   = blockIdx.x * NT;
    const int k0   = blockIdx.y * KCH;
    const int ksg0 = blockIdx.y * KSTEPS;
    const int s0   = blockIdx.y * NSTAGE;

    // ---- prologue: A fragments into smem (coalesced) ----
#pragma unroll
    for (int i = 0; i < 4; i++) {
        int idx = tid + i * 256;            // 0..1023
        int mb = idx >> 8, ks = (idx >> 5) & 7, ln = idx & 31;
        ABH[(mb * 8 + ks) * 32 + ln] = g_ah[(mb * 128 + ksg0 + ks) * 32 + ln];
    }
#pragma unroll
    for (int i = 0; i < 2; i++) {
        int idx = tid + i * 256;            // 0..511
        int mb = idx >> 7, s = (idx >> 5) & 3, ln = idx & 31;
        A8H[(mb * 4 + s) * 32 + ln] = g_a8h[(mb * 64 + s0 + s) * 32 + ln];
        A8L[(mb * 4 + s) * 32 + ln] = g_a8l[(mb * 64 + s0 + s) * 32 + ln];
    }

    // ---- W ingress mapping ----
    const int r  = tid >> 2;            // 0..63 (W row within tile)
    const int kq = (tid & 3) * 4;       // float offset within 16
    const int hq = kq >> 3;             // bf16 16B-half within kstep
    const int off8 = (kq & 4) ? 8 : 0;
    const int rsw = (r >> 2) & 1;
    const int bf_off = r * 32 + (((hq ^ rsw) & 1) << 4) + off8;  // bf16 STS.64
    const int f8_offA = r * 32 + (rsw << 4) + kq;                // fp8 wA STS.32
    const int f8_offB = r * 32 + ((rsw ^ 1) << 4) + kq;          // fp8 wB STS.32
    const float* wptr = Wv + (size_t)(n0 + r) * KDIM + k0 + kq;

    // ---- bf16 ldmatrix lane address ----
    const int nl   = ((lane >> 4) & 1) * 8 + (lane & 7);
    const int hh2  = (lane >> 3) & 1;
    const int brow = wcol * 16 + nl;
    const int ldsm_off = brow * 32 + (((hh2 ^ (brow >> 2)) & 1) << 4);

    float hh[2][2][4], cc[2][2][4];
#pragma unroll
    for (int a = 0; a < 2; a++)
#pragma unroll
        for (int b = 0; b < 2; b++)
#pragma unroll
            for (int c = 0; c < 4; c++) { hh[a][b][c] = 0.f; cc[a][b][c] = 0.f; }

    float4 wA = *reinterpret_cast<const float4*>(wptr);
    float4 wB = *reinterpret_cast<const float4*>(wptr + 16);

#pragma unroll
    for (int s = 0; s < NSTAGE; s++) {
        const int buf = s & 1;
        // convert + store W stage (wA -> kstep0/half0, wB -> kstep1/half1)
        {
            uint32_t h01, h23; float fh[4], fl[4];
            hi_lo4(wA, h01, h23, fh, fl);
            *reinterpret_cast<uint2*>(&WH[buf * 4096 + bf_off]) = make_uint2(h01, h23);
            *reinterpret_cast<uint32_t*>(&W8L[buf * 2048 + f8_offA]) =
                pack4_e4m3(fl[0] * WLS, fl[1] * WLS, fl[2] * WLS, fl[3] * WLS);
            *reinterpret_cast<uint32_t*>(&W8H[buf * 2048 + f8_offA]) =
                pack4_e4m3(fh[0] * WHS, fh[1] * WHS, fh[2] * WHS, fh[3] * WHS);

            hi_lo4(wB, h01, h23, fh, fl);
            *reinterpret_cast<uint2*>(&WH[buf * 4096 + 2048 + bf_off]) = make_uint2(h01, h23);
            *reinterpret_cast<uint32_t*>(&W8L[buf * 2048 + f8_offB]) =
                pack4_e4m3(fl[0] * WLS, fl[1] * WLS, fl[2] * WLS, fl[3] * WLS);
            *reinterpret_cast<uint32_t*>(&W8H[buf * 2048 + f8_offB]) =
                pack4_e4m3(fh[0] * WHS, fh[1] * WHS, fh[2] * WHS, fh[3] * WHS);
        }
        if (s + 1 < NSTAGE) {   // prefetch next stage W
            wA = *reinterpret_cast<const float4*>(wptr + (s + 1) * 32);
            wB = *reinterpret_cast<const float4*>(wptr + (s + 1) * 32 + 16);
        }
        __syncthreads();

        // ---- bf16 hh products (2 ksteps) ----
#pragma unroll
        for (int kk = 0; kk < 2; kk++) {
            const int ks = s * 2 + kk;
            uint4 ah0 = ABH[((wrow * 2 + 0) * 8 + ks) * 32 + lane];
            uint4 ah1 = ABH[((wrow * 2 + 1) * 8 + ks) * 32 + lane];
            uint32_t bh[4];
            ldsm4(bh, (uint32_t)__cvta_generic_to_shared(
                          &WH[buf * 4096 + kk * 2048]) + ldsm_off);
            mma_bf16(hh[0][0], ah0, bh[0], bh[1]);
            mma_bf16(hh[0][1], ah0, bh[2], bh[3]);
            mma_bf16(hh[1][0], ah1, bh[0], bh[1]);
            mma_bf16(hh[1][1], ah1, bh[2], bh[3]);
        }

        // ---- fp8 correction (one k32 step) ----
        {
            uint4 a8h0 = A8H[((wrow * 2 + 0) * 4 + s) * 32 + lane];
            uint4 a8h1 = A8H[((wrow * 2 + 1) * 4 + s) * 32 + lane];
            uint4 a8l0 = A8L[((wrow * 2 + 0) * 4 + s) * 32 + lane];
            uint4 a8l1 = A8L[((wrow * 2 + 1) * 4 + s) * 32 + lane];
#pragma unroll
            for (int nf = 0; nf < 2; nf++) {
                int nrow = wcol * 16 + nf * 8 + g;
                int sw = (nrow >> 2) & 1;
                uint32_t lb0 = *reinterpret_cast<const uint32_t*>(
                    &W8L[buf * 2048 + nrow * 32 + (sw << 4) + 4 * tt]);
                uint32_t lb1 = *reinterpret_cast<const uint32_t*>(
                    &W8L[buf * 2048 + nrow * 32 + ((sw ^ 1) << 4) + 4 * tt]);
                uint32_t hb0 = *reinterpret_cast<const uint32_t*>(
                    &W8H[buf * 2048 + nrow * 32 + (sw << 4) + 4 * tt]);
                uint32_t hb1 = *reinterpret_cast<const uint32_t*>(
                    &W8H[buf * 2048 + nrow * 32 + ((sw ^ 1) << 4) + 4 * tt]);
                mma_fp8(cc[0][nf], a8h0, lb0, lb1);   // xh * wl
                mma_fp8(cc[1][nf], a8h1, lb0, lb1);
                mma_fp8(cc[0][nf], a8l0, hb0, hb1);   // xl * wh
                mma_fp8(cc[1][nf], a8l1, hb0, hb1);
            }
        }
        __syncthreads();
    }

    // epilogue: combine + split-K atomics
#pragma unroll
    for (int mb = 0; mb < 2; mb++) {
#pragma unroll
        for (int nf = 0; nf < 2; nf++) {
            float v0 = hh[mb][nf][0] + cc[mb][nf][0] * CINV;
            float v1 = hh[mb][nf][1] + cc[mb][nf][1] * CINV;
            float v2 = hh[mb][nf][2] + cc[mb][nf][2] * CINV;
            float v3 = hh[mb][nf][3] + cc[mb][nf][3] * CINV;
            int m = (wrow * 2 + mb) * 16 + g;
            int n = n0 + wcol * 16 + nf * 8 + 2 * tt;
            atomicAdd(reinterpret_cast<float2*>(&out[m * NDIM + n]),
                      make_float2(v0, v1));
            atomicAdd(reinterpret_cast<float2*>(&out[(m + 8) * NDIM + n]),
                      make_float2(v2, v3));
        }
    }
}

extern "C" void kernel_launch(void* const* d_in, const int* in_sizes, int n_in,
                              void* d_out, int out_size) {
    // inputs: 0=x [64,1,2048] f32, 1=Wq, 2=bq, 3=Wk, 4=bk, 5=Wv [2048,2048], 6=pos
    const float* x  = (const float*)d_in[0];
    const float* Wv = (const float*)d_in[5];
    float* out = (float*)d_out;

    cudaFuncSetAttribute(gemm_kernel,
                         cudaFuncAttributeMaxDynamicSharedMemorySize, SM_TOTAL);

    convert_x_kernel<<<64, 256>>>(x, (float4*)out);
    convert_x8_kernel<<<32, 256>>>(x);
    dim3 grid(NDIM / NT, SPLITK);   // 32 x 16 = 512 CTAs
    gemm_kernel<<<grid, GT, SM_TOTAL>>>(Wv, out);

    (void)in_sizes; (void)n_in; (void)out_size;
}

// round 11
// speedup vs baseline: 1.5063x; 1.5063x over previous
#include <cuda_runtime.h>
#include <cuda_fp16.h>
#include <cstdint>

// LinearAttentionCell with T=1 reduces algebraically to out = x @ Wv^T.
// R11: fp16 2-product GEMM. mma.sync on sm_103a is MAC-rate capped at
// ~256 MACs/cyc/SM (measured invariant across R6/R8/R9), so the only lever
// is MAC count: 3-product bf16 Dekker (805M MACs, 12.1us) -> fp16 2-product
// (537M MACs, ~8.1us floor):
//   x*w = xh*wh + xh*(wl*2^11) * 2^-11   (== xh*w exactly; fp16 products are
//   exact in fp32). Error = (x - xh)*w ~ 2^-11 incoherent => rel_err ~2.5e-4.
// wl pre-scaled by 2^11 to stay in fp16 normal range; unscaled in epilogue.
// Single fused kernel: A converted from x in the prologue (L2-resident),
// W split per stage in registers. 2 graph nodes total (memset + gemm).

#define KDIM 2048
#define NDIM 2048
#define MDIM 64
#define NT   64
#define SPLITK 16
#define KCH  128
#define KSTEPS 8      // k16 steps per CTA
#define NSTAGE 4      // k32 stages per CTA
#define GT   256      // 8 warps: 2 wrow(m32) x 4 wcol(n16)
#define WLSC  2048.0f
#define WLINV (1.0f/2048.0f)

__device__ __forceinline__ uint32_t f16x2(float hi_e, float lo_e) {
    // packs: low 16 = f16(lo_e), high 16 = f16(hi_e)
    uint32_t r;
    asm("cvt.rn.f16x2.f32 %0, %1, %2;" : "=r"(r) : "f"(hi_e), "f"(lo_e));
    return r;
}

// split float4 of w into fp16 hi words + fp16 (lo*2^11) words
__device__ __forceinline__ void splitw4(float4 v, uint32_t& h01, uint32_t& h23,
                                        uint32_t& l01, uint32_t& l23) {
    h01 = f16x2(v.y, v.x);
    h23 = f16x2(v.w, v.z);
    float2 fa = __half22float2(*reinterpret_cast<__half2*>(&h01));
    float2 fb = __half22float2(*reinterpret_cast<__half2*>(&h23));
    l01 = f16x2((v.y - fa.y) * WLSC, (v.x - fa.x) * WLSC);
    l23 = f16x2((v.w - fb.y) * WLSC, (v.z - fb.x) * WLSC);
}

__device__ __forceinline__ void mma_f16(float* d, const uint32_t* a,
                                        uint32_t b0, uint32_t b1) {
    asm volatile(
        "mma.sync.aligned.m16n8k16.row.col.f32.f16.f16.f32 "
        "{%0,%1,%2,%3}, {%4,%5,%6,%7}, {%8,%9}, {%0,%1,%2,%3};"
        : "+f"(d[0]), "+f"(d[1]), "+f"(d[2]), "+f"(d[3])
        : "r"(a[0]), "r"(a[1]), "r"(a[2]), "r"(a[3]), "r"(b0), "r"(b1));
}

__device__ __forceinline__ void ldsm4(uint32_t* r, uint32_t addr) {
    asm volatile(
        "ldmatrix.sync.aligned.m8n8.x4.shared.b16 {%0,%1,%2,%3}, [%4];"
        : "=r"(r[0]), "=r"(r[1]), "=r"(r[2]), "=r"(r[3]) : "r"(addr));
}

__global__ __launch_bounds__(GT, 3)
void gemm_kernel(const float* __restrict__ x, const float* __restrict__ Wv,
                 float* __restrict__ out) {
    // fp16 tiles, each [64 rows x 16 k] = 2KB, 16B-chunk XOR swizzle
    __shared__ __align__(16) uint8_t AH[KSTEPS][2048];   // x fp16 (per kstep)
    __shared__ __align__(16) uint8_t WH[2][2][2048];     // [buf][kstep] w-hi
    __shared__ __align__(16) uint8_t WL[2][2][2048];     // [buf][kstep] w-lo*2^11

    const int tid  = threadIdx.x;
    const int lane = tid & 31;
    const int wid  = tid >> 5;
    const int wrow = wid >> 2;     // m32 group 0..1
    const int wcol = wid & 3;      // n16 group 0..3
    const int g  = lane >> 2;
    const int tt = lane & 3;

    const int n0 = blockIdx.x * NT;
    const int k0 = blockIdx.y * KCH;

    // ---- shared ingress mapping: thread -> (row r, 4-float k chunk kq) ----
    const int r   = tid >> 2;           // 0..63
    const int kq  = (tid & 3) * 4;      // 0,4,8,12 within 16-float kstep
    const int hq  = kq >> 3;            // 16B half
    const int off8 = (kq & 4) ? 8 : 0;
    const int sts_off = r * 32 + (((hq ^ (r >> 2)) & 1) << 4) + off8;

    // ---- A prologue: convert x slice [64 m x 128 k] -> fp16 tiles ----
    {
        const float* xp = x + (size_t)r * KDIM + k0 + kq;
#pragma unroll
        for (int i = 0; i < KSTEPS; i++) {
            float4 v = *reinterpret_cast<const float4*>(xp + i * 16);
            uint32_t h01 = f16x2(v.y, v.x);
            uint32_t h23 = f16x2(v.w, v.z);
            *reinterpret_cast<uint2*>(&AH[i][sts_off]) = make_uint2(h01, h23);
        }
    }

    // ---- ldmatrix lane offsets ----
    // A side: lanes 0-15 -> m rows 0-15 (k-half 0), lanes 16-31 -> k-half 1
    const int am0 = (wrow * 2 + 0) * 16 + (lane & 15);
    const int am1 = am0 + 16;
    const int akh = lane >> 4;
    const uint32_t aoff0 = am0 * 32 + (((akh ^ (am0 >> 2)) & 1) << 4);
    const uint32_t aoff1 = am1 * 32 + (((akh ^ (am1 >> 2)) & 1) << 4);
    // W side (R8-validated): matrices (n0-7,k0-7),(n0-7,k8-15),(n8-15,...)
    const int nl   = ((lane >> 4) & 1) * 8 + (lane & 7);
    const int bkh  = (lane >> 3) & 1;
    const int brow = wcol * 16 + nl;
    const uint32_t boff = brow * 32 + (((bkh ^ (brow >> 2)) & 1) << 4);

    const float* wptr = Wv + (size_t)(n0 + r) * KDIM + k0 + kq;

    float acch[2][2][4], accl[2][2][4];
#pragma unroll
    for (int a = 0; a < 2; a++)
#pragma unroll
        for (int b = 0; b < 2; b++)
#pragma unroll
            for (int c = 0; c < 4; c++) { acch[a][b][c] = 0.f; accl[a][b][c] = 0.f; }

    float4 wA = *reinterpret_cast<const float4*>(wptr);
    float4 wB = *reinterpret_cast<const float4*>(wptr + 16);

#pragma unroll
    for (int s = 0; s < NSTAGE; s++) {
        const int buf = s & 1;
        // split + store W stage (2 ksteps)
        {
            uint32_t h01, h23, l01, l23;
            splitw4(wA, h01, h23, l01, l23);
            *reinterpret_cast<uint2*>(&WH[buf][0][sts_off]) = make_uint2(h01, h23);
            *reinterpret_cast<uint2*>(&WL[buf][0][sts_off]) = make_uint2(l01, l23);
            splitw4(wB, h01, h23, l01, l23);
            *reinterpret_cast<uint2*>(&WH[buf][1][sts_off]) = make_uint2(h01, h23);
            *reinterpret_cast<uint2*>(&WL[buf][1][sts_off]) = make_uint2(l01, l23);
        }
        if (s + 1 < NSTAGE) {   // prefetch next stage (overlaps MMAs)
            wA = *reinterpret_cast<const float4*>(wptr + (s + 1) * 32);
            wB = *reinterpret_cast<const float4*>(wptr + (s + 1) * 32 + 16);
        }
        __syncthreads();

#pragma unroll
        for (int kk = 0; kk < 2; kk++) {
            const int ks = s * 2 + kk;
            uint32_t a0[4], a1[4], bh[4], bl[4];
            ldsm4(a0, (uint32_t)__cvta_generic_to_shared(&AH[ks][0]) + aoff0);
            ldsm4(a1, (uint32_t)__cvta_generic_to_shared(&AH[ks][0]) + aoff1);
            ldsm4(bh, (uint32_t)__cvta_generic_to_shared(&WH[buf][kk][0]) + boff);
            ldsm4(bl, (uint32_t)__cvta_generic_to_shared(&WL[buf][kk][0]) + boff);

            // 8 MMAs, 8 independent accumulators -> max ILP
            mma_f16(acch[0][0], a0, bh[0], bh[1]);
            mma_f16(acch[0][1], a0, bh[2], bh[3]);
            mma_f16(acch[1][0], a1, bh[0], bh[1]);
            mma_f16(acch[1][1], a1, bh[2], bh[3]);
            mma_f16(accl[0][0], a0, bl[0], bl[1]);
            mma_f16(accl[0][1], a0, bl[2], bl[3]);
            mma_f16(accl[1][0], a1, bl[0], bl[1]);
            mma_f16(accl[1][1], a1, bl[2], bl[3]);
        }
    }

    // ---- epilogue: combine scales, split-K via vector atomics ----
#pragma unroll
    for (int mb = 0; mb < 2; mb++) {
#pragma unroll
        for (int nf = 0; nf < 2; nf++) {
            float v0 = acch[mb][nf][0] + accl[mb][nf][0] * WLINV;
            float v1 = acch[mb][nf][1] + accl[mb][nf][1] * WLINV;
            float v2 = acch[mb][nf][2] + accl[mb][nf][2] * WLINV;
            float v3 = acch[mb][nf][3] + accl[mb][nf][3] * WLINV;
            int m = (wrow * 2 + mb) * 16 + g;
            int n = n0 + wcol * 16 + nf * 8 + 2 * tt;
            atomicAdd(reinterpret_cast<float2*>(&out[m * NDIM + n]),
                      make_float2(v0, v1));
            atomicAdd(reinterpret_cast<float2*>(&out[(m + 8) * NDIM + n]),
                      make_float2(v2, v3));
        }
    }
}

extern "C" void kernel_launch(void* const* d_in, const int* in_sizes, int n_in,
                              void* d_out, int out_size) {
    // inputs: 0=x [64,1,2048] f32, 1=Wq, 2=bq, 3=Wk, 4=bk, 5=Wv [2048,2048], 6=pos
    const float* x  = (const float*)d_in[0];
    const float* Wv = (const float*)d_in[5];
    float* out = (float*)d_out;

    cudaMemsetAsync(out, 0, (size_t)MDIM * NDIM * sizeof(float));
    dim3 grid(NDIM / NT, SPLITK);   // 32 x 16 = 512 CTAs
    gemm_kernel<<<grid, GT>>>(x, Wv, out);

    (void)in_sizes; (void)n_in; (void)out_size;
}